// round 1
// baseline (speedup 1.0000x reference)
#include <cuda_runtime.h>
#include <cuda_bf16.h>
#include <cstdint>
#include <cstddef>

#define D        128
#define NNODES   1000000
#define BATCH    100000
#define NITER    6
#define GATES    512          // 4*D
#define KDIM     256          // 2*D

#define BM 64
#define BN 128
#define BK 16
#define MTILES ((BATCH + BM - 1) / BM)     // 1563
#define MPAD   (MTILES * BM)               // 100032

// ---------------- device scratch (no allocations allowed) ----------------
__device__ float          g_gates[(size_t)MPAD * GATES];   // ~205 MB
__device__ float          g_h[BATCH * D];
__device__ float          g_c[BATCH * D];
__device__ float          g_r[BATCH * D];
__device__ __align__(16) __nv_bfloat16 g_Whi[GATES * KDIM];
__device__ __align__(16) __nv_bfloat16 g_Wlo[GATES * KDIM];
__device__ float          g_bias[GATES];
__device__ int            g_batch32[NNODES];
__device__ int            g_segstart[BATCH + 1];
__device__ int            g_is64;

// ---------------- batch dtype detection + conversion ----------------
// batch is sorted uniform in [0, 100000). Viewed as int32:
//   int64 case -> odd indices are high words == 0
//   int32 case -> index ~900001 holds value ~90000 != 0
__global__ void k_detect(const void* batch) {
    const int* p = (const int*)batch;
    g_is64 = (p[500001] == 0 && p[700001] == 0 && p[900001] == 0) ? 1 : 0;
}

__global__ void k_convert(const void* batch) {
    int n = blockIdx.x * blockDim.x + threadIdx.x;
    if (n >= NNODES) return;
    if (g_is64)
        g_batch32[n] = (int)((const long long*)batch)[n];
    else
        g_batch32[n] = ((const int*)batch)[n];
}

__global__ void k_segstart() {
    int n = blockIdx.x * blockDim.x + threadIdx.x;
    if (n >= NNODES) return;
    int cur  = g_batch32[n];
    int prev = (n == 0) ? -1 : g_batch32[n - 1];
    for (int b = prev + 1; b <= cur; ++b) g_segstart[b] = n;
    if (n == NNODES - 1)
        for (int b = cur + 1; b <= BATCH; ++b) g_segstart[b] = NNODES;
}

// ---------------- weight prep: Wc = [w_ih[:,:D]+w_hh | w_ih[:,D:]], split bf16 ----------------
__global__ void k_prep(const float* __restrict__ w_ih, const float* __restrict__ w_hh,
                       const float* __restrict__ b_ih, const float* __restrict__ b_hh) {
    int i = blockIdx.x * blockDim.x + threadIdx.x;
    if (i < GATES * KDIM) {
        int n = i / KDIM, k = i % KDIM;
        float w = w_ih[n * KDIM + k];
        if (k < D) w += w_hh[n * D + k];
        __nv_bfloat16 hi = __float2bfloat16(w);
        float lo = w - __bfloat162float(hi);
        g_Whi[i] = hi;
        g_Wlo[i] = __float2bfloat16(lo);
    }
    if (i < GATES) g_bias[i] = b_ih[i] + b_hh[i];
}

__global__ void k_zero() {
    int i = blockIdx.x * blockDim.x + threadIdx.x;
    if (i >= BATCH * D) return;
    g_h[i] = 0.f; g_c[i] = 0.f; g_r[i] = 0.f;
}

// ---------------- GEMM: gates[MPAD,512] = [h|r][M,256] @ Wc^T, split-bf16 mma ----------------
__device__ __forceinline__ void mma16816(float* d, const uint32_t* a, uint32_t b0, uint32_t b1) {
    asm volatile(
        "mma.sync.aligned.m16n8k16.row.col.f32.bf16.bf16.f32 "
        "{%0,%1,%2,%3}, {%4,%5,%6,%7}, {%8,%9}, {%0,%1,%2,%3};\n"
        : "+f"(d[0]), "+f"(d[1]), "+f"(d[2]), "+f"(d[3])
        : "r"(a[0]), "r"(a[1]), "r"(a[2]), "r"(a[3]), "r"(b0), "r"(b1));
}

__global__ __launch_bounds__(256) void k_gemm() {
    __shared__ __align__(16) __nv_bfloat16 sAh[BM][BK];
    __shared__ __align__(16) __nv_bfloat16 sAl[BM][BK];
    __shared__ __align__(16) __nv_bfloat16 sBh[BN][BK];
    __shared__ __align__(16) __nv_bfloat16 sBl[BN][BK];

    int bm = blockIdx.x;           // m tile
    int bn = blockIdx.y;           // n tile (0..3)
    int tid = threadIdx.x;
    int warp = tid >> 5, lane = tid & 31;
    int wm = warp & 3;             // 4 m-warps, 16 rows each
    int wn = warp >> 2;            // 2 n-warps, 64 cols each
    int g  = lane >> 2, t4 = lane & 3;

    float acc[8][4];
    #pragma unroll
    for (int s = 0; s < 8; ++s)
        #pragma unroll
        for (int j = 0; j < 4; ++j) acc[s][j] = 0.f;

    int row0 = bm * BM;

    for (int kc = 0; kc < KDIM / BK; ++kc) {
        int k0 = kc * BK;
        const float* src;
        int koff;
        if (k0 < D) { src = g_h; koff = k0; } else { src = g_r; koff = k0 - D; }

        // load + split A tile (64x16 fp32 -> hi/lo bf16)
        #pragma unroll
        for (int e = tid; e < BM * BK; e += 256) {
            int r = e >> 4, kk = e & 15;
            int grow = row0 + r;
            float v = (grow < BATCH) ? src[(size_t)grow * D + koff + kk] : 0.f;
            __nv_bfloat16 hi = __float2bfloat16(v);
            sAh[r][kk] = hi;
            sAl[r][kk] = __float2bfloat16(v - __bfloat162float(hi));
        }
        // load B tile (128 n-rows x 16 k, hi/lo), u32 granularity
        #pragma unroll
        for (int e = tid; e < BN * BK / 2; e += 256) {
            int nn  = e >> 3;
            int kk2 = e & 7;
            int gn  = bn * BN + nn;
            const uint32_t* ph = (const uint32_t*)&g_Whi[(size_t)gn * KDIM + k0];
            const uint32_t* pl = (const uint32_t*)&g_Wlo[(size_t)gn * KDIM + k0];
            ((uint32_t*)&sBh[nn][0])[kk2] = ph[kk2];
            ((uint32_t*)&sBl[nn][0])[kk2] = pl[kk2];
        }
        __syncthreads();

        uint32_t ah[4], al[4];
        int ar = wm * 16 + g;
        ah[0] = *(const uint32_t*)&sAh[ar    ][t4 * 2    ];
        ah[1] = *(const uint32_t*)&sAh[ar + 8][t4 * 2    ];
        ah[2] = *(const uint32_t*)&sAh[ar    ][t4 * 2 + 8];
        ah[3] = *(const uint32_t*)&sAh[ar + 8][t4 * 2 + 8];
        al[0] = *(const uint32_t*)&sAl[ar    ][t4 * 2    ];
        al[1] = *(const uint32_t*)&sAl[ar + 8][t4 * 2    ];
        al[2] = *(const uint32_t*)&sAl[ar    ][t4 * 2 + 8];
        al[3] = *(const uint32_t*)&sAl[ar + 8][t4 * 2 + 8];

        #pragma unroll
        for (int s = 0; s < 8; ++s) {
            int nn = wn * 64 + s * 8 + g;
            uint32_t bh0 = *(const uint32_t*)&sBh[nn][t4 * 2    ];
            uint32_t bh1 = *(const uint32_t*)&sBh[nn][t4 * 2 + 8];
            uint32_t bl0 = *(const uint32_t*)&sBl[nn][t4 * 2    ];
            uint32_t bl1 = *(const uint32_t*)&sBl[nn][t4 * 2 + 8];
            mma16816(acc[s], ah, bh0, bh1);   // hi*hi
            mma16816(acc[s], ah, bl0, bl1);   // hi*lo
            mma16816(acc[s], al, bh0, bh1);   // lo*hi
        }
        __syncthreads();
    }

    // store gates (padded scratch: no row guard needed)
    #pragma unroll
    for (int s = 0; s < 8; ++s) {
        int col = bn * BN + wn * 64 + s * 8 + t4 * 2;
        size_t r0 = (size_t)(row0 + wm * 16 + g);
        size_t r1 = r0 + 8;
        g_gates[r0 * GATES + col    ] = acc[s][0];
        g_gates[r0 * GATES + col + 1] = acc[s][1];
        g_gates[r1 * GATES + col    ] = acc[s][2];
        g_gates[r1 * GATES + col + 1] = acc[s][3];
    }
}

// ---------------- LSTM epilogue: activations + (h,c) update ----------------
__global__ void k_lstm_epi() {
    int i = blockIdx.x * blockDim.x + threadIdx.x;
    if (i >= BATCH * D) return;
    int r = i >> 7, d = i & 127;
    const float* grow = &g_gates[(size_t)r * GATES];
    float gi = grow[d          ] + g_bias[d          ];
    float gf = grow[d + 128    ] + g_bias[d + 128    ];
    float gg = grow[d + 256    ] + g_bias[d + 256    ];
    float go = grow[d + 384    ] + g_bias[d + 384    ];
    float si = 1.f / (1.f + expf(-gi));
    float sf = 1.f / (1.f + expf(-gf));
    float tg = tanhf(gg);
    float so = 1.f / (1.f + expf(-go));
    float c  = sf * g_c[i] + si * tg;
    g_c[i] = c;
    g_h[i] = so * tanhf(c);
}

// ---------------- attention: warp-per-segment online softmax + readout ----------------
#define WPB  8
#define ECAP 64
__global__ __launch_bounds__(WPB * 32) void k_attn(const float* __restrict__ x) {
    __shared__ float e_s[WPB][ECAP];
    int warp = threadIdx.x >> 5, lane = threadIdx.x & 31;
    int b = blockIdx.x * WPB + warp;
    if (b >= BATCH) return;

    int s0 = g_segstart[b], s1 = g_segstart[b + 1];
    float4 hv = ((const float4*)g_h)[b * 32 + lane];
    const float4* x4 = (const float4*)x;

    float m = -1e30f, ssum = 0.f;
    for (int n = s0; n < s1; ++n) {
        float4 xv = x4[(size_t)n * 32 + lane];
        float p = xv.x * hv.x + xv.y * hv.y + xv.z * hv.z + xv.w * hv.w;
        #pragma unroll
        for (int off = 16; off > 0; off >>= 1)
            p += __shfl_xor_sync(0xffffffffu, p, off);
        float e = p;
        if (lane == 0 && (n - s0) < ECAP) e_s[warp][n - s0] = e;
        float mn = fmaxf(m, e);
        ssum = ssum * expf(m - mn) + expf(e - mn);
        m = mn;
    }
    __syncwarp();

    float inv = (s1 > s0) ? 1.f / ssum : 0.f;
    float4 acc = make_float4(0.f, 0.f, 0.f, 0.f);
    for (int n = s0; n < s1; ++n) {
        float4 xv = x4[(size_t)n * 32 + lane];
        float e;
        if ((n - s0) < ECAP) {
            e = e_s[warp][n - s0];
        } else {   // pathological long segment: recompute
            float p = xv.x * hv.x + xv.y * hv.y + xv.z * hv.z + xv.w * hv.w;
            #pragma unroll
            for (int off = 16; off > 0; off >>= 1)
                p += __shfl_xor_sync(0xffffffffu, p, off);
            e = p;
        }
        float a = expf(e - m) * inv;
        acc.x += a * xv.x; acc.y += a * xv.y; acc.z += a * xv.z; acc.w += a * xv.w;
    }
    ((float4*)g_r)[b * 32 + lane] = acc;
}

// ---------------- final output: q_star = [h | readout] ----------------
__global__ void k_out(float* __restrict__ out) {
    int i = blockIdx.x * blockDim.x + threadIdx.x;
    if (i >= BATCH * D) return;
    int r = i >> 7, d = i & 127;
    out[(size_t)r * 256 + d      ] = g_h[i];
    out[(size_t)r * 256 + 128 + d] = g_r[i];
}

// ---------------- launch ----------------
extern "C" void kernel_launch(void* const* d_in, const int* in_sizes, int n_in,
                              void* d_out, int out_size) {
    const float* x    = (const float*)d_in[0];
    const void*  batch=               d_in[1];
    const float* w_ih = (const float*)d_in[2];
    const float* w_hh = (const float*)d_in[3];
    const float* b_ih = (const float*)d_in[4];
    const float* b_hh = (const float*)d_in[5];
    (void)in_sizes; (void)n_in; (void)out_size;

    k_detect<<<1, 1>>>(batch);
    k_convert<<<(NNODES + 255) / 256, 256>>>(batch);
    k_segstart<<<(NNODES + 255) / 256, 256>>>();
    k_prep<<<(GATES * KDIM + 255) / 256, 256>>>(w_ih, w_hh, b_ih, b_hh);
    k_zero<<<(BATCH * D + 255) / 256, 256>>>();

    dim3 gg(MTILES, GATES / BN);
    for (int it = 0; it < NITER; ++it) {
        k_gemm<<<gg, 256>>>();
        k_lstm_epi<<<(BATCH * D + 255) / 256, 256>>>();
        k_attn<<<(BATCH + WPB - 1) / WPB, WPB * 32>>>(x);
    }
    k_out<<<(BATCH * D + 255) / 256, 256>>>((float*)d_out);
}